// round 1
// baseline (speedup 1.0000x reference)
#include <cuda_runtime.h>
#include <cstdint>

#define N_NODES  131072
#define N_EDGES  2097152
#define F_IN     32
#define HID      64
#define G_FEAT   16
#define N_GRAPHS 1024
#define BN_EPS   1e-5f

// ---------------- device scratch (no allocations allowed) ----------------
__device__ float g_deg[N_NODES];
__device__ float g_dinv[N_NODES];
__device__ float g_y[(size_t)N_NODES * HID];
__device__ float g_acc[(size_t)N_NODES * HID];
__device__ float g_z[(size_t)N_NODES * HID];
__device__ float g_h[(size_t)N_NODES * HID];
__device__ float g_bnsum[HID];
__device__ float g_bnsumsq[HID];
__device__ float g_scale[HID];
__device__ float g_shift[HID];
__device__ int   g_cnt[N_GRAPHS];
__device__ int   g_start[N_GRAPHS];
__device__ float g_pooled[(size_t)N_GRAPHS * HID];

// ---------------- zero kernels ----------------
__global__ void zero_small_kernel() {
    int t = blockIdx.x * 256 + threadIdx.x;
    if (t < N_NODES) g_deg[t] = 0.f;
    if (t < HID) { g_bnsum[t] = 0.f; g_bnsumsq[t] = 0.f; }
    if (t < N_GRAPHS) g_cnt[t] = 0;
}

__global__ void zero_stats_kernel() {
    int t = threadIdx.x;
    if (t < HID) { g_bnsum[t] = 0.f; g_bnsumsq[t] = 0.f; }
}

__global__ void zero_acc_kernel() {
    size_t i = ((size_t)blockIdx.x * 256 + threadIdx.x) * 4;
    if (i < (size_t)N_NODES * HID)
        *(float4*)(g_acc + i) = make_float4(0.f, 0.f, 0.f, 0.f);
}

// ---------------- degree ----------------
__global__ void deg_kernel(const int* __restrict__ ei) {
    int e = blockIdx.x * 256 + threadIdx.x;
    if (e < N_EDGES) {
        int d = __ldg(ei + N_EDGES + e);
        float one = 1.0f;
        asm volatile("red.global.add.f32 [%0], %1;" :: "l"(g_deg + d), "f"(one) : "memory");
    }
}

__global__ void dinv_kernel() {
    int n = blockIdx.x * 256 + threadIdx.x;
    if (n < N_NODES) g_dinv[n] = rsqrtf(g_deg[n] + 1.0f);
}

// ---------------- y = (X @ W) * dinv ----------------
template <int K, bool USE_H>
__global__ __launch_bounds__(128) void xw_kernel(const float* __restrict__ xin,
                                                 const float* __restrict__ W) {
    __shared__ float sW[K * HID];
    for (int i = threadIdx.x; i < K * HID; i += 128) sW[i] = W[i];
    __syncthreads();
    int n = blockIdx.x * 128 + threadIdx.x;
    if (n >= N_NODES) return;
    const float* row = USE_H ? (g_h + (size_t)n * HID) : (xin + (size_t)n * K);
    float acc[HID];
#pragma unroll
    for (int j = 0; j < HID; j++) acc[j] = 0.f;
#pragma unroll 4
    for (int k = 0; k < K; k++) {
        float xv = row[k];
#pragma unroll
        for (int j = 0; j < HID; j++) acc[j] += xv * sW[k * HID + j];
    }
    float d = g_dinv[n];
    float* out = g_y + (size_t)n * HID;
#pragma unroll
    for (int j = 0; j < HID; j++) out[j] = acc[j] * d;
}

// ---------------- edge scatter: acc[dst] += y[src] ----------------
__global__ __launch_bounds__(256) void scatter_kernel(const int* __restrict__ ei) {
    unsigned tid = blockIdx.x * 256u + threadIdx.x;
    unsigned e = tid >> 4;          // edge
    unsigned c = tid & 15u;         // float4 chunk (16 * 4 = 64 feats)
    if (e >= N_EDGES) return;
    int src = __ldg(ei + e);
    int dst = __ldg(ei + N_EDGES + e);
    float4 v = *(const float4*)(g_y + (size_t)src * HID + c * 4);
    float* p = g_acc + (size_t)dst * HID + c * 4;
    asm volatile("red.global.add.v4.f32 [%0], {%1,%2,%3,%4};"
                 :: "l"(p), "f"(v.x), "f"(v.y), "f"(v.z), "f"(v.w) : "memory");
}

// ---------------- z = dinv*(acc + y) + b ; accumulate BN stats ----------------
__global__ __launch_bounds__(256) void stats_kernel(const float* __restrict__ b) {
    int f = threadIdx.x & 63;
    int sub = threadIdx.x >> 6;         // 0..3
    int base = blockIdx.x * 512;        // 256 blocks * 512 nodes = N_NODES
    float bf = b[f];
    float s = 0.f, ss = 0.f;
    for (int i = sub; i < 512; i += 4) {
        int n = base + i;
        size_t idx = (size_t)n * HID + f;
        float val = g_dinv[n] * (g_acc[idx] + g_y[idx]) + bf;
        g_z[idx] = val;
        s += val;
        ss += val * val;
    }
    __shared__ float sh1[4][64], sh2[4][64];
    sh1[sub][f] = s; sh2[sub][f] = ss;
    __syncthreads();
    if (sub == 0) {
        s = sh1[0][f] + sh1[1][f] + sh1[2][f] + sh1[3][f];
        ss = sh2[0][f] + sh2[1][f] + sh2[2][f] + sh2[3][f];
        atomicAdd(&g_bnsum[f], s);
        atomicAdd(&g_bnsumsq[f], ss);
    }
}

__global__ void bnfin_kernel(const float* __restrict__ gamma,
                             const float* __restrict__ beta) {
    int f = threadIdx.x;
    if (f >= HID) return;
    const float inv_n = 1.0f / (float)N_NODES;
    float mu = g_bnsum[f] * inv_n;
    float var = g_bnsumsq[f] * inv_n - mu * mu;
    float rstd = rsqrtf(var + BN_EPS);
    float sc = rstd * gamma[f];
    g_scale[f] = sc;
    g_shift[f] = beta[f] - mu * sc;
}

// ---------------- h = relu(z*scale + shift) ----------------
__global__ void norm_kernel() {
    size_t i = ((size_t)blockIdx.x * 256 + threadIdx.x) * 4;
    if (i >= (size_t)N_NODES * HID) return;
    float4 z = *(const float4*)(g_z + i);
    int f = (int)(i & 63);
    z.x = fmaxf(z.x * g_scale[f + 0] + g_shift[f + 0], 0.f);
    z.y = fmaxf(z.y * g_scale[f + 1] + g_shift[f + 1], 0.f);
    z.z = fmaxf(z.z * g_scale[f + 2] + g_shift[f + 2], 0.f);
    z.w = fmaxf(z.w * g_scale[f + 3] + g_shift[f + 3], 0.f);
    *(float4*)(g_h + i) = z;
}

// ---------------- pooling ----------------
__global__ void count_kernel(const int* __restrict__ batch) {
    int n = blockIdx.x * 256 + threadIdx.x;
    if (n < N_NODES) atomicAdd(&g_cnt[batch[n]], 1);
}

__global__ void prefix_kernel() {
    __shared__ int sh[N_GRAPHS];
    int t = threadIdx.x;
    int c = g_cnt[t];
    sh[t] = c;
    __syncthreads();
    for (int off = 1; off < N_GRAPHS; off <<= 1) {
        int v = (t >= off) ? sh[t - off] : 0;
        __syncthreads();
        sh[t] += v;
        __syncthreads();
    }
    g_start[t] = sh[t] - c;   // exclusive prefix
}

__global__ __launch_bounds__(256) void pool_kernel() {
    int idx = blockIdx.x * 256 + threadIdx.x;  // N_GRAPHS * HID = 65536
    if (idx >= N_GRAPHS * HID) return;
    int g = idx >> 6, f = idx & 63;
    int s = g_start[g], c = g_cnt[g];
    float sum = 0.f;
    for (int i = 0; i < c; i++) sum += g_h[(size_t)(s + i) * HID + f];
    g_pooled[idx] = sum / (float)max(c, 1);
}

// ---------------- final MLP heads (one warp per graph) ----------------
__global__ __launch_bounds__(256) void mlp_kernel(
    const float* __restrict__ gf,
    const float* __restrict__ Wo1, const float* __restrict__ bo1,
    const float* __restrict__ Wo2, const float* __restrict__ bo2,
    const float* __restrict__ Wb1, const float* __restrict__ bb1,
    const float* __restrict__ Wb2, const float* __restrict__ bb2,
    float* __restrict__ out) {
    int warp = (blockIdx.x * 256 + threadIdx.x) >> 5;
    int lane = threadIdx.x & 31;
    if (warp >= N_GRAPHS) return;
    int g = warp;
    // hidden dim is HID/2 = 32 == warp size; lane j computes hidden unit j
    float hO = bo1[lane], hB = bb1[lane];
#pragma unroll 4
    for (int i = 0; i < HID + G_FEAT; i++) {
        float ci = (i < HID) ? g_pooled[(size_t)g * HID + i]
                             : gf[(size_t)g * G_FEAT + (i - HID)];
        hO += ci * Wo1[i * 32 + lane];
        hB += ci * Wb1[i * 32 + lane];
    }
    hO = fmaxf(hO, 0.f);
    hB = fmaxf(hB, 0.f);
    float vO = hO * Wo2[lane];
    float vB = hB * Wb2[lane];
#pragma unroll
    for (int off = 16; off; off >>= 1) {
        vO += __shfl_down_sync(0xffffffffu, vO, off);
        vB += __shfl_down_sync(0xffffffffu, vB, off);
    }
    if (lane == 0) {
        out[g] = vO + bo2[0];
        out[N_GRAPHS + g] = vB + bb2[0];
    }
}

// ---------------- launch ----------------
extern "C" void kernel_launch(void* const* d_in, const int* in_sizes, int n_in,
                              void* d_out, int out_size) {
    const float* x      = (const float*)d_in[0];
    const int*   ei     = (const int*)  d_in[1];
    const int*   batch  = (const int*)  d_in[2];
    const float* gfeat  = (const float*)d_in[3];
    const float* W1     = (const float*)d_in[4];
    const float* b1     = (const float*)d_in[5];
    const float* gamma1 = (const float*)d_in[6];
    const float* beta1  = (const float*)d_in[7];
    const float* W2     = (const float*)d_in[8];
    const float* b2     = (const float*)d_in[9];
    const float* gamma2 = (const float*)d_in[10];
    const float* beta2  = (const float*)d_in[11];
    const float* Wo1    = (const float*)d_in[12];
    const float* bo1    = (const float*)d_in[13];
    const float* Wo2    = (const float*)d_in[14];
    const float* bo2    = (const float*)d_in[15];
    const float* Wb1    = (const float*)d_in[16];
    const float* bb1    = (const float*)d_in[17];
    const float* Wb2    = (const float*)d_in[18];
    const float* bb2    = (const float*)d_in[19];
    float* out = (float*)d_out;

    const int ZB_ACC   = (int)(((size_t)N_NODES * HID / 4 + 255) / 256); // 8192
    const int EB       = (N_EDGES + 255) / 256;                          // 8192
    const int NB       = (N_NODES + 255) / 256;                          // 512
    const int SCATTERB = (int)(((size_t)N_EDGES * 16 + 255) / 256);      // 131072
    const int NORMB    = ZB_ACC;

    // init
    zero_small_kernel<<<NB, 256>>>();
    zero_acc_kernel<<<ZB_ACC, 256>>>();
    deg_kernel<<<EB, 256>>>(ei);
    dinv_kernel<<<NB, 256>>>();

    // ---- layer 1 ----
    xw_kernel<F_IN, false><<<N_NODES / 128, 128>>>(x, W1);
    scatter_kernel<<<SCATTERB, 256>>>(ei);
    stats_kernel<<<256, 256>>>(b1);
    bnfin_kernel<<<1, 64>>>(gamma1, beta1);
    norm_kernel<<<NORMB, 256>>>();

    // ---- layer 2 ----
    zero_acc_kernel<<<ZB_ACC, 256>>>();
    zero_stats_kernel<<<1, 64>>>();
    xw_kernel<HID, true><<<N_NODES / 128, 128>>>(nullptr, W2);
    scatter_kernel<<<SCATTERB, 256>>>(ei);
    stats_kernel<<<256, 256>>>(b2);
    bnfin_kernel<<<1, 64>>>(gamma2, beta2);
    norm_kernel<<<NORMB, 256>>>();

    // ---- pooling + heads ----
    count_kernel<<<NB, 256>>>(batch);
    prefix_kernel<<<1, N_GRAPHS>>>();
    pool_kernel<<<N_GRAPHS * HID / 256, 256>>>();
    mlp_kernel<<<N_GRAPHS / 8, 256>>>(gfeat, Wo1, bo1, Wo2, bo2,
                                      Wb1, bb1, Wb2, bb2, out);
}